// round 2
// baseline (speedup 1.0000x reference)
#include <cuda_runtime.h>

#define BB 8
#define NU 1024
#define NI 2048
#define NN 3072
#define DD 64
#define CE 192   // (L+1)*D concat width

// Scratch (static device allocations -- allowed)
__device__ float g_all_e[(size_t)BB * NN * CE];  // concat embeddings: [b][n][0:64|64:128|128:192]
__device__ float g_side[(size_t)BB * NN * DD];   // adj @ ego buffer

// ---------------------------------------------------------------------------
// 1) Gather: ego0 = concat(user_table[u_idx], item_table[i_idx]) -> all_e[:,:,0:64]
// ---------------------------------------------------------------------------
__global__ void gather_kernel(const int* __restrict__ uidx, const int* __restrict__ iidx,
                              const float* __restrict__ utab, const float* __restrict__ itab) {
    int tid = blockIdx.x * blockDim.x + threadIdx.x;
    if (tid >= BB * NN * DD) return;
    int d = tid & 63;
    int r = (tid >> 6) % NN;
    int b = tid / (NN * DD);
    float v;
    if (r < NU) v = utab[(size_t)uidx[b * NU + r] * DD + d];
    else        v = itab[(size_t)iidx[b * NI + (r - NU)] * DD + d];
    g_all_e[((size_t)(b * NN + r)) * CE + d] = v;
}

// ---------------------------------------------------------------------------
// 2a) side[b] = adj[b] @ ego_l[b]   (M=3072, K=3072, N=64)
//     64x64 block tile, BK=32, 256 threads, 4x4 microtile per thread.
// ---------------------------------------------------------------------------
__global__ __launch_bounds__(256) void adj_gemm_kernel(const float* __restrict__ adj, int l) {
    __shared__ float As[64 * 33];                     // [m][k], pad 33 -> conflict-free
    __shared__ __align__(16) float Bs[32 * 64];       // [k][n]
    int b  = blockIdx.y;
    int m0 = blockIdx.x * 64;
    int t  = threadIdx.x;
    int tx = t & 15, ty = t >> 4;

    const float* egob = g_all_e + (size_t)b * NN * CE + (size_t)l * DD;  // row stride CE
    const float* adjb = adj + (size_t)b * NN * NN;

    float acc[4][4] = {};

    for (int k0 = 0; k0 < NN; k0 += 32) {
        #pragma unroll
        for (int i = 0; i < 8; i++) {
            int m = (t >> 5) + i * 8;
            int k = t & 31;
            As[m * 33 + k] = adjb[(size_t)(m0 + m) * NN + k0 + k];
        }
        #pragma unroll
        for (int i = 0; i < 8; i++) {
            int idx = t + i * 256;
            int k = idx >> 6;
            int n = idx & 63;
            Bs[k * 64 + n] = egob[(size_t)(k0 + k) * CE + n];
        }
        __syncthreads();
        #pragma unroll
        for (int kk = 0; kk < 32; kk++) {
            float a0 = As[(ty * 4 + 0) * 33 + kk];
            float a1 = As[(ty * 4 + 1) * 33 + kk];
            float a2 = As[(ty * 4 + 2) * 33 + kk];
            float a3 = As[(ty * 4 + 3) * 33 + kk];
            float4 bv = *(const float4*)&Bs[kk * 64 + tx * 4];
            acc[0][0] += a0 * bv.x; acc[0][1] += a0 * bv.y; acc[0][2] += a0 * bv.z; acc[0][3] += a0 * bv.w;
            acc[1][0] += a1 * bv.x; acc[1][1] += a1 * bv.y; acc[1][2] += a1 * bv.z; acc[1][3] += a1 * bv.w;
            acc[2][0] += a2 * bv.x; acc[2][1] += a2 * bv.y; acc[2][2] += a2 * bv.z; acc[2][3] += a2 * bv.w;
            acc[3][0] += a3 * bv.x; acc[3][1] += a3 * bv.y; acc[3][2] += a3 * bv.z; acc[3][3] += a3 * bv.w;
        }
        __syncthreads();
    }

    #pragma unroll
    for (int i = 0; i < 4; i++) {
        float* outp = g_side + ((size_t)(b * NN + m0 + ty * 4 + i)) * DD + tx * 4;
        float4 v = make_float4(acc[i][0], acc[i][1], acc[i][2], acc[i][3]);
        *(float4*)outp = v;
    }
}

// ---------------------------------------------------------------------------
// 2b) Per-node layer transform:
//     s  = lrelu(side @ gc_w[l]^T + gc_b[l])
//     bi = lrelu((ego*side) @ bi_w[l]^T + bi_b[l])
//     ego_{l+1} = s + bi   -> all_e[:,:, (l+1)*64 : (l+2)*64]
//     4 nodes per 256-thread block.
// ---------------------------------------------------------------------------
__global__ __launch_bounds__(256) void layer_kernel(const float* __restrict__ gc_w,
                                                    const float* __restrict__ gc_b,
                                                    const float* __restrict__ bi_w,
                                                    const float* __restrict__ bi_b, int l) {
    __shared__ float s_gcw[64 * 65];
    __shared__ float s_biw[64 * 65];
    __shared__ float s_side[4 * 64];
    __shared__ float s_ego[4 * 64];
    __shared__ float s_gcb[64], s_bib[64];

    int t = threadIdx.x;
    int node0 = blockIdx.x * 4;  // global node index over B*NN

    #pragma unroll
    for (int i = 0; i < 16; i++) {
        int idx = t + i * 256;
        int r = idx >> 6, c = idx & 63;
        s_gcw[r * 65 + c] = gc_w[l * 4096 + idx];
        s_biw[r * 65 + c] = bi_w[l * 4096 + idx];
    }
    if (t < 64) { s_gcb[t] = gc_b[l * 64 + t]; s_bib[t] = bi_b[l * 64 + t]; }
    {
        int i = t >> 6, k = t & 63;
        size_t gn = node0 + i;
        float sv = g_side[gn * DD + k];
        s_side[i * 64 + k] = sv;
        s_ego[i * 64 + k]  = g_all_e[gn * CE + (size_t)l * DD + k];
    }
    __syncthreads();

    int i = t >> 6, j = t & 63;
    size_t gn = node0 + i;
    float s  = s_gcb[j];
    float bi = s_bib[j];
    #pragma unroll
    for (int k = 0; k < 64; k++) {
        float sv = s_side[i * 64 + k];
        s  += sv * s_gcw[j * 65 + k];
        bi += (s_ego[i * 64 + k] * sv) * s_biw[j * 65 + k];
    }
    s  = (s  > 0.f) ? s  : 0.01f * s;
    bi = (bi > 0.f) ? bi : 0.01f * bi;
    g_all_e[gn * CE + (size_t)(l + 1) * DD + j] = s + bi;
}

// ---------------------------------------------------------------------------
// 3) scores[b] = U[b] @ I[b]^T   (M=1024, N=2048, K=192)  -> d_out
// ---------------------------------------------------------------------------
__global__ __launch_bounds__(256) void scores_kernel(float* __restrict__ out) {
    __shared__ float Us[64 * 33];   // [m][k]
    __shared__ float Is[64 * 33];   // [j][k]
    int b  = blockIdx.z;
    int m0 = blockIdx.y * 64;
    int j0 = blockIdx.x * 64;
    int t  = threadIdx.x;
    int tx = t & 15, ty = t >> 4;

    const float* U = g_all_e + (size_t)b * NN * CE;               // users: rows 0..1023
    const float* I = g_all_e + ((size_t)b * NN + NU) * CE;        // items: rows 0..2047

    float acc[4][4] = {};

    for (int k0 = 0; k0 < CE; k0 += 32) {
        #pragma unroll
        for (int i = 0; i < 8; i++) {
            int m = (t >> 5) + i * 8;
            int k = t & 31;
            Us[m * 33 + k] = U[(size_t)(m0 + m) * CE + k0 + k];
            Is[m * 33 + k] = I[(size_t)(j0 + m) * CE + k0 + k];
        }
        __syncthreads();
        #pragma unroll
        for (int kk = 0; kk < 32; kk++) {
            float a0 = Us[(ty * 4 + 0) * 33 + kk];
            float a1 = Us[(ty * 4 + 1) * 33 + kk];
            float a2 = Us[(ty * 4 + 2) * 33 + kk];
            float a3 = Us[(ty * 4 + 3) * 33 + kk];
            float b0 = Is[(tx * 4 + 0) * 33 + kk];
            float b1 = Is[(tx * 4 + 1) * 33 + kk];
            float b2 = Is[(tx * 4 + 2) * 33 + kk];
            float b3 = Is[(tx * 4 + 3) * 33 + kk];
            acc[0][0] += a0 * b0; acc[0][1] += a0 * b1; acc[0][2] += a0 * b2; acc[0][3] += a0 * b3;
            acc[1][0] += a1 * b0; acc[1][1] += a1 * b1; acc[1][2] += a1 * b2; acc[1][3] += a1 * b3;
            acc[2][0] += a2 * b0; acc[2][1] += a2 * b1; acc[2][2] += a2 * b2; acc[2][3] += a2 * b3;
            acc[3][0] += a3 * b0; acc[3][1] += a3 * b1; acc[3][2] += a3 * b2; acc[3][3] += a3 * b3;
        }
        __syncthreads();
    }

    #pragma unroll
    for (int i = 0; i < 4; i++) {
        float* outp = out + ((size_t)b * NU + m0 + ty * 4 + i) * NI + j0 + tx * 4;
        float4 v = make_float4(acc[i][0], acc[i][1], acc[i][2], acc[i][3]);
        *(float4*)outp = v;
    }
}

// ---------------------------------------------------------------------------
// 4) In-place row log-softmax over 2048 items. One block per row.
// ---------------------------------------------------------------------------
__global__ __launch_bounds__(256) void logsoftmax_kernel(float* __restrict__ out) {
    size_t row = blockIdx.x;
    float* p = out + row * NI;
    int t = threadIdx.x;

    float v[8];
    float mx = -3.4e38f;
    #pragma unroll
    for (int i = 0; i < 8; i++) { v[i] = p[t + i * 256]; mx = fmaxf(mx, v[i]); }

    __shared__ float red[8];
    #pragma unroll
    for (int o = 16; o; o >>= 1) mx = fmaxf(mx, __shfl_xor_sync(0xffffffffu, mx, o));
    if ((t & 31) == 0) red[t >> 5] = mx;
    __syncthreads();
    if (t < 32) {
        float m2 = (t < 8) ? red[t] : -3.4e38f;
        #pragma unroll
        for (int o = 4; o; o >>= 1) m2 = fmaxf(m2, __shfl_xor_sync(0xffffffffu, m2, o));
        if (t == 0) red[0] = m2;
    }
    __syncthreads();
    float bm = red[0];
    __syncthreads();

    float sum = 0.f;
    #pragma unroll
    for (int i = 0; i < 8; i++) sum += __expf(v[i] - bm);
    #pragma unroll
    for (int o = 16; o; o >>= 1) sum += __shfl_xor_sync(0xffffffffu, sum, o);
    if ((t & 31) == 0) red[t >> 5] = sum;
    __syncthreads();
    if (t < 32) {
        float s2 = (t < 8) ? red[t] : 0.f;
        #pragma unroll
        for (int o = 4; o; o >>= 1) s2 += __shfl_xor_sync(0xffffffffu, s2, o);
        if (t == 0) red[0] = s2;
    }
    __syncthreads();
    float lse = bm + logf(red[0]);

    #pragma unroll
    for (int i = 0; i < 8; i++) p[t + i * 256] = v[i] - lse;
}

// ---------------------------------------------------------------------------
extern "C" void kernel_launch(void* const* d_in, const int* in_sizes, int n_in,
                              void* d_out, int out_size) {
    const int*   uidx = (const int*)d_in[0];
    const int*   iidx = (const int*)d_in[1];
    const float* adj  = (const float*)d_in[2];
    const float* utab = (const float*)d_in[3];
    const float* itab = (const float*)d_in[4];
    const float* gc_w = (const float*)d_in[5];
    const float* gc_b = (const float*)d_in[6];
    const float* bi_w = (const float*)d_in[7];
    const float* bi_b = (const float*)d_in[8];
    float* out = (float*)d_out;

    gather_kernel<<<(BB * NN * DD + 255) / 256, 256>>>(uidx, iidx, utab, itab);

    for (int l = 0; l < 2; l++) {
        dim3 g(NN / 64, BB);
        adj_gemm_kernel<<<g, 256>>>(adj, l);
        layer_kernel<<<BB * NN / 4, 256>>>(gc_w, gc_b, bi_w, bi_b, l);
    }

    dim3 gs(NI / 64, NU / 64, BB);
    scores_kernel<<<gs, 256>>>(out);

    logsoftmax_kernel<<<BB * NU, 256>>>(out);
}

// round 4
// speedup vs baseline: 1.2657x; 1.2657x over previous
#include <cuda_runtime.h>
#include <cstdint>

#define BB 8
#define NU 1024
#define NI 2048
#define NN 3072
#define DD 64
#define CE 192   // (L+1)*D concat width

// Scratch (static device allocations -- allowed)
__device__ __align__(16) float g_all_e[(size_t)BB * NN * CE];
__device__ __align__(16) float g_side[(size_t)BB * NN * DD];

// ===========================================================================
// TF32 helpers (arch-neutral PTX, sm_80+)
// ===========================================================================
__device__ __forceinline__ uint32_t f2tf32(float x) {
    uint32_t h;
    asm("cvt.rna.tf32.f32 %0, %1;" : "=r"(h) : "f"(x));
    return h;
}
__device__ __forceinline__ void split3(float x, uint32_t& hi, uint32_t& lo) {
    hi = f2tf32(x);
    lo = f2tf32(x - __uint_as_float(hi));
}
__device__ __forceinline__ void mma8(float* c, const uint32_t* a, const uint32_t* b) {
    asm volatile("mma.sync.aligned.m16n8k8.row.col.f32.tf32.tf32.f32 "
                 "{%0,%1,%2,%3}, {%4,%5,%6,%7}, {%8,%9}, {%0,%1,%2,%3};"
                 : "+f"(c[0]), "+f"(c[1]), "+f"(c[2]), "+f"(c[3])
                 : "r"(a[0]), "r"(a[1]), "r"(a[2]), "r"(a[3]), "r"(b[0]), "r"(b[1]));
}

#define AST 36   // A smem row stride (floats): 4m+k bank map -> conflict-free frags
#define BST 68   // B smem row stride (floats): 4k+n bank map -> <=2-way

// ---------------------------------------------------------------------------
// 1) Gather
// ---------------------------------------------------------------------------
__global__ void gather_kernel(const int* __restrict__ uidx, const int* __restrict__ iidx,
                              const float* __restrict__ utab, const float* __restrict__ itab) {
    int tid = blockIdx.x * blockDim.x + threadIdx.x;
    if (tid >= BB * NN * DD) return;
    int d = tid & 63;
    int r = (tid >> 6) % NN;
    int b = tid / (NN * DD);
    float v;
    if (r < NU) v = utab[(size_t)uidx[b * NU + r] * DD + d];
    else        v = itab[(size_t)iidx[b * NI + (r - NU)] * DD + d];
    g_all_e[((size_t)(b * NN + r)) * CE + d] = v;
}

// ---------------------------------------------------------------------------
// 2a) side[b] = adj[b] @ ego_l[b]  (M=3072, K=3072, N=64) via mma.sync 3xTF32
//     CTA 64x64, BK=32, 8 warps (2M x 4N), warp tile 32x16.
// ---------------------------------------------------------------------------
__global__ __launch_bounds__(256) void adj_gemm_mma(const float* __restrict__ adj, int l) {
    __shared__ uint32_t Ahi[64 * AST], Alo[64 * AST];
    __shared__ uint32_t Bhi[32 * BST], Blo[32 * BST];

    int t = threadIdx.x, lane = t & 31, wid = t >> 5;
    int b = blockIdx.y, m0 = blockIdx.x * 64;
    const float* adjb = adj + (size_t)b * NN * NN;
    const float* egob = g_all_e + (size_t)b * NN * CE + (size_t)l * DD;

    int wm = (wid & 1) * 32, wn = (wid >> 1) * 16;
    float acc[2][2][4] = {};

    // producer mapping
    int ar0 = t >> 3, ak0 = (t & 7) * 4;     // A: (row, 4k), rows ar0 and ar0+32
    int bk0 = t >> 4, bn0 = (t & 15) * 4;    // B: (k, 4n), ks bk0 and bk0+16

    float4 pa0, pa1, pb0, pb1;
    pa0 = *(const float4*)(adjb + (size_t)(m0 + ar0) * NN + ak0);
    pa1 = *(const float4*)(adjb + (size_t)(m0 + ar0 + 32) * NN + ak0);
    pb0 = *(const float4*)(egob + (size_t)bk0 * CE + bn0);
    pb1 = *(const float4*)(egob + (size_t)(bk0 + 16) * CE + bn0);

    #pragma unroll 1
    for (int it = 0; it < NN / 32; ++it) {
        // split + store current tile
        {
            uint32_t h[4], lw[4];
            split3(pa0.x, h[0], lw[0]); split3(pa0.y, h[1], lw[1]);
            split3(pa0.z, h[2], lw[2]); split3(pa0.w, h[3], lw[3]);
            *(uint4*)&Ahi[ar0 * AST + ak0] = make_uint4(h[0], h[1], h[2], h[3]);
            *(uint4*)&Alo[ar0 * AST + ak0] = make_uint4(lw[0], lw[1], lw[2], lw[3]);
            split3(pa1.x, h[0], lw[0]); split3(pa1.y, h[1], lw[1]);
            split3(pa1.z, h[2], lw[2]); split3(pa1.w, h[3], lw[3]);
            *(uint4*)&Ahi[(ar0 + 32) * AST + ak0] = make_uint4(h[0], h[1], h[2], h[3]);
            *(uint4*)&Alo[(ar0 + 32) * AST + ak0] = make_uint4(lw[0], lw[1], lw[2], lw[3]);
            split3(pb0.x, h[0], lw[0]); split3(pb0.y, h[1], lw[1]);
            split3(pb0.z, h[2], lw[2]); split3(pb0.w, h[3], lw[3]);
            *(uint4*)&Bhi[bk0 * BST + bn0] = make_uint4(h[0], h[1], h[2], h[3]);
            *(uint4*)&Blo[bk0 * BST + bn0] = make_uint4(lw[0], lw[1], lw[2], lw[3]);
            split3(pb1.x, h[0], lw[0]); split3(pb1.y, h[1], lw[1]);
            split3(pb1.z, h[2], lw[2]); split3(pb1.w, h[3], lw[3]);
            *(uint4*)&Bhi[(bk0 + 16) * BST + bn0] = make_uint4(h[0], h[1], h[2], h[3]);
            *(uint4*)&Blo[(bk0 + 16) * BST + bn0] = make_uint4(lw[0], lw[1], lw[2], lw[3]);
        }
        __syncthreads();

        // prefetch next tile into regs (hidden under MMA phase)
        if (it + 1 < NN / 32) {
            int k0 = (it + 1) * 32;
            pa0 = *(const float4*)(adjb + (size_t)(m0 + ar0) * NN + k0 + ak0);
            pa1 = *(const float4*)(adjb + (size_t)(m0 + ar0 + 32) * NN + k0 + ak0);
            pb0 = *(const float4*)(egob + (size_t)(k0 + bk0) * CE + bn0);
            pb1 = *(const float4*)(egob + (size_t)(k0 + bk0 + 16) * CE + bn0);
        }

        // MMA phase
        #pragma unroll
        for (int kt = 0; kt < 4; kt++) {
            uint32_t aH[2][4], aL[2][4], bH[2][2], bL[2][2];
            #pragma unroll
            for (int mt = 0; mt < 2; mt++) {
                int r = wm + mt * 16 + (lane >> 2);
                int c = kt * 8 + (lane & 3);
                aH[mt][0] = Ahi[r * AST + c];         aH[mt][1] = Ahi[(r + 8) * AST + c];
                aH[mt][2] = Ahi[r * AST + c + 4];     aH[mt][3] = Ahi[(r + 8) * AST + c + 4];
                aL[mt][0] = Alo[r * AST + c];         aL[mt][1] = Alo[(r + 8) * AST + c];
                aL[mt][2] = Alo[r * AST + c + 4];     aL[mt][3] = Alo[(r + 8) * AST + c + 4];
            }
            #pragma unroll
            for (int nt = 0; nt < 2; nt++) {
                int k = kt * 8 + (lane & 3);
                int n = wn + nt * 8 + (lane >> 2);
                bH[nt][0] = Bhi[k * BST + n];  bH[nt][1] = Bhi[(k + 4) * BST + n];
                bL[nt][0] = Blo[k * BST + n];  bL[nt][1] = Blo[(k + 4) * BST + n];
            }
            #pragma unroll
            for (int mt = 0; mt < 2; mt++)
                #pragma unroll
                for (int nt = 0; nt < 2; nt++) {
                    mma8(acc[mt][nt], aH[mt], bH[nt]);
                    mma8(acc[mt][nt], aH[mt], bL[nt]);
                    mma8(acc[mt][nt], aL[mt], bH[nt]);
                }
        }
        __syncthreads();
    }

    // epilogue
    #pragma unroll
    for (int mt = 0; mt < 2; mt++) {
        int r = m0 + wm + mt * 16 + (lane >> 2);
        #pragma unroll
        for (int nt = 0; nt < 2; nt++) {
            int cc = wn + nt * 8 + (lane & 3) * 2;
            float* o = g_side + ((size_t)b * NN + r) * DD + cc;
            *(float2*)o = make_float2(acc[mt][nt][0], acc[mt][nt][1]);
            *(float2*)(o + 8 * DD) = make_float2(acc[mt][nt][2], acc[mt][nt][3]);
        }
    }
}

// ---------------------------------------------------------------------------
// 2b) Per-node layer transform
// ---------------------------------------------------------------------------
__global__ __launch_bounds__(256) void layer_kernel(const float* __restrict__ gc_w,
                                                    const float* __restrict__ gc_b,
                                                    const float* __restrict__ bi_w,
                                                    const float* __restrict__ bi_b, int l) {
    __shared__ float s_gcw[64 * 65];
    __shared__ float s_biw[64 * 65];
    __shared__ float s_side[4 * 64];
    __shared__ float s_ego[4 * 64];
    __shared__ float s_gcb[64], s_bib[64];

    int t = threadIdx.x;
    int node0 = blockIdx.x * 4;

    #pragma unroll
    for (int i = 0; i < 16; i++) {
        int idx = t + i * 256;
        int r = idx >> 6, c = idx & 63;
        s_gcw[r * 65 + c] = gc_w[l * 4096 + idx];
        s_biw[r * 65 + c] = bi_w[l * 4096 + idx];
    }
    if (t < 64) { s_gcb[t] = gc_b[l * 64 + t]; s_bib[t] = bi_b[l * 64 + t]; }
    {
        int i = t >> 6, k = t & 63;
        size_t gn = node0 + i;
        s_side[i * 64 + k] = g_side[gn * DD + k];
        s_ego[i * 64 + k]  = g_all_e[gn * CE + (size_t)l * DD + k];
    }
    __syncthreads();

    int i = t >> 6, j = t & 63;
    size_t gn = node0 + i;
    float s  = s_gcb[j];
    float bi = s_bib[j];
    #pragma unroll
    for (int k = 0; k < 64; k++) {
        float sv = s_side[i * 64 + k];
        s  += sv * s_gcw[j * 65 + k];
        bi += (s_ego[i * 64 + k] * sv) * s_biw[j * 65 + k];
    }
    s  = (s  > 0.f) ? s  : 0.01f * s;
    bi = (bi > 0.f) ? bi : 0.01f * bi;
    g_all_e[gn * CE + (size_t)(l + 1) * DD + j] = s + bi;
}

// ---------------------------------------------------------------------------
// 3) scores[b] = U @ I^T  (M=1024, N=2048, K=192) via mma.sync 3xTF32
//    CTA 64x64, BK=32. Both A and B are K-major rows.
// ---------------------------------------------------------------------------
__global__ __launch_bounds__(256) void scores_mma(float* __restrict__ out) {
    __shared__ uint32_t Ahi[64 * AST], Alo[64 * AST];
    __shared__ uint32_t Bhi[64 * AST], Blo[64 * AST];

    int t = threadIdx.x, lane = t & 31, wid = t >> 5;
    int b = blockIdx.z, m0 = blockIdx.y * 64, j0 = blockIdx.x * 64;

    const float* U = g_all_e + (size_t)b * NN * CE;
    const float* I = g_all_e + ((size_t)b * NN + NU) * CE;

    int wm = (wid & 1) * 32, wn = (wid >> 1) * 16;
    float acc[2][2][4] = {};

    int r0 = t >> 3, kq0 = (t & 7) * 4;  // rows r0 and r0+32, 4 k's

    float4 pa0, pa1, pb0, pb1;
    pa0 = *(const float4*)(U + (size_t)(m0 + r0) * CE + kq0);
    pa1 = *(const float4*)(U + (size_t)(m0 + r0 + 32) * CE + kq0);
    pb0 = *(const float4*)(I + (size_t)(j0 + r0) * CE + kq0);
    pb1 = *(const float4*)(I + (size_t)(j0 + r0 + 32) * CE + kq0);

    #pragma unroll 1
    for (int it = 0; it < CE / 32; ++it) {
        {
            uint32_t h[4], lw[4];
            split3(pa0.x, h[0], lw[0]); split3(pa0.y, h[1], lw[1]);
            split3(pa0.z, h[2], lw[2]); split3(pa0.w, h[3], lw[3]);
            *(uint4*)&Ahi[r0 * AST + kq0] = make_uint4(h[0], h[1], h[2], h[3]);
            *(uint4*)&Alo[r0 * AST + kq0] = make_uint4(lw[0], lw[1], lw[2], lw[3]);
            split3(pa1.x, h[0], lw[0]); split3(pa1.y, h[1], lw[1]);
            split3(pa1.z, h[2], lw[2]); split3(pa1.w, h[3], lw[3]);
            *(uint4*)&Ahi[(r0 + 32) * AST + kq0] = make_uint4(h[0], h[1], h[2], h[3]);
            *(uint4*)&Alo[(r0 + 32) * AST + kq0] = make_uint4(lw[0], lw[1], lw[2], lw[3]);
            split3(pb0.x, h[0], lw[0]); split3(pb0.y, h[1], lw[1]);
            split3(pb0.z, h[2], lw[2]); split3(pb0.w, h[3], lw[3]);
            *(uint4*)&Bhi[r0 * AST + kq0] = make_uint4(h[0], h[1], h[2], h[3]);
            *(uint4*)&Blo[r0 * AST + kq0] = make_uint4(lw[0], lw[1], lw[2], lw[3]);
            split3(pb1.x, h[0], lw[0]); split3(pb1.y, h[1], lw[1]);
            split3(pb1.z, h[2], lw[2]); split3(pb1.w, h[3], lw[3]);
            *(uint4*)&Bhi[(r0 + 32) * AST + kq0] = make_uint4(h[0], h[1], h[2], h[3]);
            *(uint4*)&Blo[(r0 + 32) * AST + kq0] = make_uint4(lw[0], lw[1], lw[2], lw[3]);
        }
        __syncthreads();

        if (it + 1 < CE / 32) {
            int k0 = (it + 1) * 32;
            pa0 = *(const float4*)(U + (size_t)(m0 + r0) * CE + k0 + kq0);
            pa1 = *(const float4*)(U + (size_t)(m0 + r0 + 32) * CE + k0 + kq0);
            pb0 = *(const float4*)(I + (size_t)(j0 + r0) * CE + k0 + kq0);
            pb1 = *(const float4*)(I + (size_t)(j0 + r0 + 32) * CE + k0 + kq0);
        }

        #pragma unroll
        for (int kt = 0; kt < 4; kt++) {
            uint32_t aH[2][4], aL[2][4], bH[2][2], bL[2][2];
            #pragma unroll
            for (int mt = 0; mt < 2; mt++) {
                int r = wm + mt * 16 + (lane >> 2);
                int c = kt * 8 + (lane & 3);
                aH[mt][0] = Ahi[r * AST + c];         aH[mt][1] = Ahi[(r + 8) * AST + c];
                aH[mt][2] = Ahi[r * AST + c + 4];     aH[mt][3] = Ahi[(r + 8) * AST + c + 4];
                aL[mt][0] = Alo[r * AST + c];         aL[mt][1] = Alo[(r + 8) * AST + c];
                aL[mt][2] = Alo[r * AST + c + 4];     aL[mt][3] = Alo[(r + 8) * AST + c + 4];
            }
            #pragma unroll
            for (int nt = 0; nt < 2; nt++) {
                int n = wn + nt * 8 + (lane >> 2);
                int c = kt * 8 + (lane & 3);
                bH[nt][0] = Bhi[n * AST + c];  bH[nt][1] = Bhi[n * AST + c + 4];
                bL[nt][0] = Blo[n * AST + c];  bL[nt][1] = Blo[n * AST + c + 4];
            }
            #pragma unroll
            for (int mt = 0; mt < 2; mt++)
                #pragma unroll
                for (int nt = 0; nt < 2; nt++) {
                    mma8(acc[mt][nt], aH[mt], bH[nt]);
                    mma8(acc[mt][nt], aH[mt], bL[nt]);
                    mma8(acc[mt][nt], aL[mt], bH[nt]);
                }
        }
        __syncthreads();
    }

    #pragma unroll
    for (int mt = 0; mt < 2; mt++) {
        int r = m0 + wm + mt * 16 + (lane >> 2);
        #pragma unroll
        for (int nt = 0; nt < 2; nt++) {
            int cc = j0 + wn + nt * 8 + (lane & 3) * 2;
            float* o = out + ((size_t)b * NU + r) * NI + cc;
            *(float2*)o = make_float2(acc[mt][nt][0], acc[mt][nt][1]);
            *(float2*)(o + 8 * NI) = make_float2(acc[mt][nt][2], acc[mt][nt][3]);
        }
    }
}

// ---------------------------------------------------------------------------
// 4) In-place row log-softmax over 2048 items.
// ---------------------------------------------------------------------------
__global__ __launch_bounds__(256) void logsoftmax_kernel(float* __restrict__ out) {
    size_t row = blockIdx.x;
    float* p = out + row * NI;
    int t = threadIdx.x;

    float v[8];
    float mx = -3.4e38f;
    #pragma unroll
    for (int i = 0; i < 8; i++) { v[i] = p[t + i * 256]; mx = fmaxf(mx, v[i]); }

    __shared__ float red[8];
    #pragma unroll
    for (int o = 16; o; o >>= 1) mx = fmaxf(mx, __shfl_xor_sync(0xffffffffu, mx, o));
    if ((t & 31) == 0) red[t >> 5] = mx;
    __syncthreads();
    if (t < 32) {
        float m2 = (t < 8) ? red[t] : -3.4e38f;
        #pragma unroll
        for (int o = 4; o; o >>= 1) m2 = fmaxf(m2, __shfl_xor_sync(0xffffffffu, m2, o));
        if (t == 0) red[0] = m2;
    }
    __syncthreads();
    float bm = red[0];
    __syncthreads();

    float sum = 0.f;
    #pragma unroll
    for (int i = 0; i < 8; i++) sum += __expf(v[i] - bm);
    #pragma unroll
    for (int o = 16; o; o >>= 1) sum += __shfl_xor_sync(0xffffffffu, sum, o);
    if ((t & 31) == 0) red[t >> 5] = sum;
    __syncthreads();
    if (t < 32) {
        float s2 = (t < 8) ? red[t] : 0.f;
        #pragma unroll
        for (int o = 4; o; o >>= 1) s2 += __shfl_xor_sync(0xffffffffu, s2, o);
        if (t == 0) red[0] = s2;
    }
    __syncthreads();
    float lse = bm + logf(red[0]);

    #pragma unroll
    for (int i = 0; i < 8; i++) p[t + i * 256] = v[i] - lse;
}

// ---------------------------------------------------------------------------
extern "C" void kernel_launch(void* const* d_in, const int* in_sizes, int n_in,
                              void* d_out, int out_size) {
    const int*   uidx = (const int*)d_in[0];
    const int*   iidx = (const int*)d_in[1];
    const float* adj  = (const float*)d_in[2];
    const float* utab = (const float*)d_in[3];
    const float* itab = (const float*)d_in[4];
    const float* gc_w = (const float*)d_in[5];
    const float* gc_b = (const float*)d_in[6];
    const float* bi_w = (const float*)d_in[7];
    const float* bi_b = (const float*)d_in[8];
    float* out = (float*)d_out;

    gather_kernel<<<(BB * NN * DD + 255) / 256, 256>>>(uidx, iidx, utab, itab);

    for (int l = 0; l < 2; l++) {
        dim3 g(NN / 64, BB);
        adj_gemm_mma<<<g, 256>>>(adj, l);
        layer_kernel<<<BB * NN / 4, 256>>>(gc_w, gc_b, bi_w, bi_b, l);
    }

    dim3 gs(NI / 64, NU / 64, BB);
    scores_mma<<<gs, 256>>>(out);

    logsoftmax_kernel<<<BB * NU, 256>>>(out);
}